// round 8
// baseline (speedup 1.0000x reference)
#include <cuda_runtime.h>

// ---------------------------------------------------------------------------
// 2-layer GCN:  out = A_n * relu(BN(A_n * (x@W1))) @ W2 + b2
// A_n = D^-1/2 (A + I) D^-1/2,  deg from dst side (+ self loop)
// ---------------------------------------------------------------------------

#define NMAX  100000
#define EMAX  1600000
#define D_IN  128
#define D_H   64
#define D_OUT 32
#define BN_EPS 1e-5f

__device__ int   g_deg[NMAX];
__device__ float g_dinv[NMAX];
__device__ float g_h0[(size_t)NMAX * D_H];   // x @ W1           (pre-agg)
__device__ float g_h1[(size_t)NMAX * D_H];   // aggregated layer1
__device__ float g_h2[(size_t)NMAX * D_OUT]; // act(h1) @ W2     (pre-agg)
__device__ float g_stats[2 * D_H];           // [sum | sumsq]
__device__ float g_scale[D_H];               // gamma * invstd
__device__ float g_shift[D_H];               // beta - mean*scale

// ------------------------------ degree / norm ------------------------------

__global__ void k_zero_deg(int n) {
    int t = blockIdx.x * blockDim.x + threadIdx.x;
    if (t < n) g_deg[t] = 0;
}

__global__ void k_deg(const int* __restrict__ dst, int e) {
    int stride = gridDim.x * blockDim.x;
    for (int t = blockIdx.x * blockDim.x + threadIdx.x; t < e; t += stride)
        atomicAdd(&g_deg[dst[t]], 1);
}

__global__ void k_dinv(int n) {
    int t = blockIdx.x * blockDim.x + threadIdx.x;
    if (t < 2 * D_H) g_stats[t] = 0.f;           // reset BN stats every call
    if (t < n) g_dinv[t] = rsqrtf((float)(g_deg[t] + 1));  // +1 self-loop
}

// ------------------------------ GEMM1: h0 = x @ W1 -------------------------
// Block tile 128x64 (full N), 128 threads, each thread 8x8, K chunked by 16.

__global__ void __launch_bounds__(128) k_gemm1(const float* __restrict__ x,
                                               const float* __restrict__ W1,
                                               int n) {
    __shared__ float As[128][17];   // [m][kk], pad 17 -> conflict-free reads
    __shared__ float Bs[16][64];    // [kk][n]

    const int tid = threadIdx.x;
    const int ty  = tid >> 3;       // 0..15  (8 rows each)
    const int tx  = tid & 7;        // 0..7   (8 cols each)
    const int m0  = blockIdx.x * 128;

    float acc[8][8];
#pragma unroll
    for (int i = 0; i < 8; i++)
#pragma unroll
        for (int j = 0; j < 8; j++) acc[i][j] = 0.f;

    for (int k0 = 0; k0 < D_IN; k0 += 16) {
        // A tile: 128 rows x 16 k  (512 float4 / 128 thr = 4 each)
#pragma unroll
        for (int p = 0; p < 4; p++) {
            int q  = p * 128 + tid;
            int m  = q >> 2, kq = q & 3;
            int gm = min(m0 + m, n - 1);
            float4 v = *(const float4*)(x + (size_t)gm * D_IN + k0 + kq * 4);
            As[m][kq * 4 + 0] = v.x;
            As[m][kq * 4 + 1] = v.y;
            As[m][kq * 4 + 2] = v.z;
            As[m][kq * 4 + 3] = v.w;
        }
        // B tile: 16 x 64 (256 float4 / 128 thr = 2 each)
#pragma unroll
        for (int p = 0; p < 2; p++) {
            int q = p * 128 + tid;
            int kk = q >> 4, nq = q & 15;
            *(float4*)&Bs[kk][nq * 4] =
                *(const float4*)(W1 + (size_t)(k0 + kk) * D_H + nq * 4);
        }
        __syncthreads();

#pragma unroll
        for (int kk = 0; kk < 16; kk++) {
            float a[8], b[8];
#pragma unroll
            for (int i = 0; i < 8; i++) a[i] = As[ty * 8 + i][kk];
            float4 b0 = *(float4*)&Bs[kk][tx * 8];
            float4 b1 = *(float4*)&Bs[kk][tx * 8 + 4];
            b[0]=b0.x; b[1]=b0.y; b[2]=b0.z; b[3]=b0.w;
            b[4]=b1.x; b[5]=b1.y; b[6]=b1.z; b[7]=b1.w;
#pragma unroll
            for (int i = 0; i < 8; i++)
#pragma unroll
                for (int j = 0; j < 8; j++) acc[i][j] += a[i] * b[j];
        }
        __syncthreads();
    }

#pragma unroll
    for (int i = 0; i < 8; i++) {
        int row = m0 + ty * 8 + i;
        if (row < n) {
            float4 o0 = make_float4(acc[i][0], acc[i][1], acc[i][2], acc[i][3]);
            float4 o1 = make_float4(acc[i][4], acc[i][5], acc[i][6], acc[i][7]);
            *(float4*)(g_h0 + (size_t)row * D_H + tx * 8)     = o0;
            *(float4*)(g_h0 + (size_t)row * D_H + tx * 8 + 4) = o1;
        }
    }
}

// ---------------- prefill1: h1 = h0 * dinv^2 (self-loop, no memset) --------

__global__ void k_pre1(int n) {
    int total = n * (D_H / 4);
    int stride = gridDim.x * blockDim.x;
    for (int t = blockIdx.x * blockDim.x + threadIdx.x; t < total; t += stride) {
        int row = t >> 4;                       // 16 float4 per row
        float di = g_dinv[row];
        float w = di * di;
        float4 v = ((const float4*)g_h0)[t];
        v.x *= w; v.y *= w; v.z *= w; v.w *= w;
        ((float4*)g_h1)[t] = v;
    }
}

// ---------------- agg1: h1[dst] += h0[src] * dinv[s]*dinv[d] ----------------
// One warp per edge; lane handles 2 channels (float2 -> 256B coalesced gather)

__global__ void k_agg1(const int* __restrict__ src,
                       const int* __restrict__ dst, int e) {
    int wid  = (blockIdx.x * blockDim.x + threadIdx.x) >> 5;
    int lane = threadIdx.x & 31;
    int nw   = (gridDim.x * blockDim.x) >> 5;
    for (int ed = wid; ed < e; ed += nw) {
        int s = __ldg(src + ed);
        int d = __ldg(dst + ed);
        float w = g_dinv[s] * g_dinv[d];
        float2 v = ((const float2*)(g_h0 + (size_t)s * D_H))[lane];
        atomicAdd(&g_h1[(size_t)d * D_H + 2 * lane],     v.x * w);
        atomicAdd(&g_h1[(size_t)d * D_H + 2 * lane + 1], v.y * w);
    }
}

// ------------------------------ BN statistics ------------------------------

__global__ void k_stats(int n) {
    __shared__ float ss[D_H], sq[D_H];
    int tid = threadIdx.x;                 // 256 threads
    if (tid < D_H) { ss[tid] = 0.f; sq[tid] = 0.f; }
    __syncthreads();

    int c  = tid & (D_H - 1);
    int r0 = blockIdx.x * 4 + (tid >> 6);  // 4 row-groups per block
    int rstride = gridDim.x * 4;
    float s = 0.f, s2 = 0.f;
    for (int r = r0; r < n; r += rstride) {
        float v = g_h1[(size_t)r * D_H + c];
        s += v; s2 += v * v;
    }
    atomicAdd(&ss[c], s);
    atomicAdd(&sq[c], s2);
    __syncthreads();
    if (tid < D_H) {
        atomicAdd(&g_stats[tid], ss[tid]);
        atomicAdd(&g_stats[D_H + tid], sq[tid]);
    }
}

__global__ void k_finalize(const float* __restrict__ gamma,
                           const float* __restrict__ beta, float inv_n) {
    int c = threadIdx.x;                   // 64 threads
    float mean = g_stats[c] * inv_n;
    float var  = g_stats[D_H + c] * inv_n - mean * mean;
    float inv  = rsqrtf(var + BN_EPS);
    float sc   = gamma[c] * inv;
    g_scale[c] = sc;
    g_shift[c] = beta[c] - mean * sc;      // (b1 cancels inside BN exactly)
}

// -------------- GEMM2: h2 = relu(h1*scale + shift) @ W2 (fused BN) ---------
// Block tile 128x32, 128 threads, thread tile 4x8, whole K=64 in smem.

__global__ void __launch_bounds__(128) k_gemm2(const float* __restrict__ W2,
                                               int n) {
    __shared__ float As[128][69];          // 64 used, pad for conflict-free
    __shared__ float Bs[64][32];
    __shared__ float s_sc[D_H], s_sh[D_H];

    const int tid = threadIdx.x;
    const int m0  = blockIdx.x * 128;

    if (tid < D_H) { s_sc[tid] = g_scale[tid]; s_sh[tid] = g_shift[tid]; }
    __syncthreads();

    // A tile: one row per thread, apply BN + ReLU on load
    {
        int gm = min(m0 + tid, n - 1);
        const float4* rp = (const float4*)(g_h1 + (size_t)gm * D_H);
#pragma unroll
        for (int kq = 0; kq < 16; kq++) {
            float4 v = rp[kq];
            int k = kq * 4;
            As[tid][k + 0] = fmaxf(fmaf(v.x, s_sc[k + 0], s_sh[k + 0]), 0.f);
            As[tid][k + 1] = fmaxf(fmaf(v.y, s_sc[k + 1], s_sh[k + 1]), 0.f);
            As[tid][k + 2] = fmaxf(fmaf(v.z, s_sc[k + 2], s_sh[k + 2]), 0.f);
            As[tid][k + 3] = fmaxf(fmaf(v.w, s_sc[k + 3], s_sh[k + 3]), 0.f);
        }
    }
    // B tile: 64x32 = 512 float4 / 128 thr = 4 each
#pragma unroll
    for (int p = 0; p < 4; p++) {
        int q = p * 128 + tid;
        int kk = q >> 3, nq = q & 7;
        *(float4*)&Bs[kk][nq * 4] =
            *(const float4*)(W2 + (size_t)kk * D_OUT + nq * 4);
    }
    __syncthreads();

    const int ty = tid >> 2;               // 0..31 (4 rows each)
    const int tx = tid & 3;                // 0..3  (8 cols each)
    float acc[4][8];
#pragma unroll
    for (int i = 0; i < 4; i++)
#pragma unroll
        for (int j = 0; j < 8; j++) acc[i][j] = 0.f;

#pragma unroll
    for (int kk = 0; kk < D_H; kk++) {
        float a[4], b[8];
#pragma unroll
        for (int i = 0; i < 4; i++) a[i] = As[ty * 4 + i][kk];
        float4 b0 = *(float4*)&Bs[kk][tx * 8];
        float4 b1 = *(float4*)&Bs[kk][tx * 8 + 4];
        b[0]=b0.x; b[1]=b0.y; b[2]=b0.z; b[3]=b0.w;
        b[4]=b1.x; b[5]=b1.y; b[6]=b1.z; b[7]=b1.w;
#pragma unroll
        for (int i = 0; i < 4; i++)
#pragma unroll
            for (int j = 0; j < 8; j++) acc[i][j] += a[i] * b[j];
    }

#pragma unroll
    for (int i = 0; i < 4; i++) {
        int row = m0 + ty * 4 + i;
        if (row < n) {
            float4 o0 = make_float4(acc[i][0], acc[i][1], acc[i][2], acc[i][3]);
            float4 o1 = make_float4(acc[i][4], acc[i][5], acc[i][6], acc[i][7]);
            *(float4*)(g_h2 + (size_t)row * D_OUT + tx * 8)     = o0;
            *(float4*)(g_h2 + (size_t)row * D_OUT + tx * 8 + 4) = o1;
        }
    }
}

// ---------- prefill2: out = h2 * dinv^2 + b2 (self-loop + bias) -------------

__global__ void k_pre2(int n, float* __restrict__ out,
                       const float* __restrict__ b2) {
    int total = n * (D_OUT / 4);
    int stride = gridDim.x * blockDim.x;
    for (int t = blockIdx.x * blockDim.x + threadIdx.x; t < total; t += stride) {
        int row = t >> 3;                   // 8 float4 per row
        int cq  = t & 7;
        float di = g_dinv[row];
        float w = di * di;
        float4 v = ((const float4*)g_h2)[t];
        float4 b = ((const float4*)b2)[cq];
        v.x = fmaf(v.x, w, b.x);
        v.y = fmaf(v.y, w, b.y);
        v.z = fmaf(v.z, w, b.z);
        v.w = fmaf(v.w, w, b.w);
        ((float4*)out)[t] = v;
    }
}

// ---------------- agg2: out[dst] += h2[src] * dinv[s]*dinv[d] ---------------
// Half-warp per edge; lane handles float2 (128B coalesced gather per edge)

__global__ void k_agg2(const int* __restrict__ src,
                       const int* __restrict__ dst, int e,
                       float* __restrict__ out) {
    int hw = (blockIdx.x * blockDim.x + threadIdx.x) >> 4;
    int j  = threadIdx.x & 15;
    int nh = (gridDim.x * blockDim.x) >> 4;
    for (int ed = hw; ed < e; ed += nh) {
        int s = __ldg(src + ed);
        int d = __ldg(dst + ed);
        float w = g_dinv[s] * g_dinv[d];
        float2 v = ((const float2*)(g_h2 + (size_t)s * D_OUT))[j];
        atomicAdd(&out[(size_t)d * D_OUT + 2 * j],     v.x * w);
        atomicAdd(&out[(size_t)d * D_OUT + 2 * j + 1], v.y * w);
    }
}

// ---------------------------------------------------------------------------

extern "C" void kernel_launch(void* const* d_in, const int* in_sizes, int n_in,
                              void* d_out, int out_size) {
    const float* x     = (const float*)d_in[0];
    const int*   edge  = (const int*)  d_in[1];
    const float* W1    = (const float*)d_in[2];
    // d_in[3] = b1 : cancels exactly inside batchnorm, unused
    const float* gamma = (const float*)d_in[4];
    const float* beta  = (const float*)d_in[5];
    const float* W2    = (const float*)d_in[6];
    const float* b2    = (const float*)d_in[7];
    float* out = (float*)d_out;

    const int n = in_sizes[0] / D_IN;
    const int e = in_sizes[1] / 2;
    const int* src = edge;       // edge_index[0]
    const int* dst = edge + e;   // edge_index[1]

    // degrees + symmetric norm
    k_zero_deg<<<(n + 255) / 256, 256>>>(n);
    k_deg<<<2048, 256>>>(dst, e);
    k_dinv<<<(n + 255) / 256, 256>>>(n);

    // layer 1
    k_gemm1<<<(n + 127) / 128, 128>>>(x, W1, n);
    k_pre1<<<2048, 256>>>(n);
    k_agg1<<<4096, 256>>>(src, dst, e);

    // batchnorm stats
    k_stats<<<256, 256>>>(n);
    k_finalize<<<1, 64>>>(gamma, beta, 1.0f / (float)n);

    // layer 2 (BN + ReLU fused into GEMM2 A-load)
    k_gemm2<<<(n + 127) / 128, 128>>>(W2, n);
    k_pre2<<<2048, 256>>>(n, out, b2);
    k_agg2<<<4096, 256>>>(src, dst, e, out);
}

// round 9
// speedup vs baseline: 1.5338x; 1.5338x over previous
#include <cuda_runtime.h>

// ---------------------------------------------------------------------------
// 2-layer GCN:  out = A_n * relu(BN(A_n * (x@W1))) @ W2 + b2
// A_n = D^-1/2 (A + I) D^-1/2,  deg from dst side (+ self loop)
// ---------------------------------------------------------------------------

#define NMAX  100000
#define EMAX  1600000
#define D_IN  128
#define D_H   64
#define D_OUT 32
#define BN_EPS 1e-5f

__device__ int   g_deg[NMAX];
__device__ float g_dinv[NMAX];
__device__ float g_h0[(size_t)NMAX * D_H];   // x @ W1           (pre-agg)
__device__ float g_h1[(size_t)NMAX * D_H];   // aggregated layer1
__device__ float g_h2[(size_t)NMAX * D_OUT]; // act(h1) @ W2     (pre-agg)
__device__ float g_stats[2 * D_H];           // [sum | sumsq]
__device__ float g_scale[D_H];               // gamma * invstd
__device__ float g_shift[D_H];               // beta - mean*scale

// ------------------------------ degree / norm ------------------------------

__global__ void k_zero_deg(int n) {
    int t = blockIdx.x * blockDim.x + threadIdx.x;
    if (t < n) g_deg[t] = 0;
}

__global__ void k_deg(const int* __restrict__ dst, int e) {
    int stride = gridDim.x * blockDim.x;
    for (int t = blockIdx.x * blockDim.x + threadIdx.x; t < e; t += stride)
        atomicAdd(&g_deg[dst[t]], 1);
}

__global__ void k_dinv(int n) {
    int t = blockIdx.x * blockDim.x + threadIdx.x;
    if (t < 2 * D_H) g_stats[t] = 0.f;           // reset BN stats every call
    if (t < n) g_dinv[t] = rsqrtf((float)(g_deg[t] + 1));  // +1 self-loop
}

// ------------------------------ GEMM1: h0 = x @ W1 -------------------------
// Block tile 128x64 (full N), 128 threads, each thread 8x8, K chunked by 16.

__global__ void __launch_bounds__(128) k_gemm1(const float* __restrict__ x,
                                               const float* __restrict__ W1,
                                               int n) {
    __shared__ float As[128][17];   // [m][kk], pad 17 -> conflict-free reads
    __shared__ float Bs[16][64];    // [kk][n]

    const int tid = threadIdx.x;
    const int ty  = tid >> 3;       // 0..15  (8 rows each)
    const int tx  = tid & 7;        // 0..7   (8 cols each)
    const int m0  = blockIdx.x * 128;

    float acc[8][8];
#pragma unroll
    for (int i = 0; i < 8; i++)
#pragma unroll
        for (int j = 0; j < 8; j++) acc[i][j] = 0.f;

    for (int k0 = 0; k0 < D_IN; k0 += 16) {
        // A tile: 128 rows x 16 k  (512 float4 / 128 thr = 4 each)
#pragma unroll
        for (int p = 0; p < 4; p++) {
            int q  = p * 128 + tid;
            int m  = q >> 2, kq = q & 3;
            int gm = min(m0 + m, n - 1);
            float4 v = *(const float4*)(x + (size_t)gm * D_IN + k0 + kq * 4);
            As[m][kq * 4 + 0] = v.x;
            As[m][kq * 4 + 1] = v.y;
            As[m][kq * 4 + 2] = v.z;
            As[m][kq * 4 + 3] = v.w;
        }
        // B tile: 16 x 64 (256 float4 / 128 thr = 2 each)
#pragma unroll
        for (int p = 0; p < 2; p++) {
            int q = p * 128 + tid;
            int kk = q >> 4, nq = q & 15;
            *(float4*)&Bs[kk][nq * 4] =
                *(const float4*)(W1 + (size_t)(k0 + kk) * D_H + nq * 4);
        }
        __syncthreads();

#pragma unroll
        for (int kk = 0; kk < 16; kk++) {
            float a[8], b[8];
#pragma unroll
            for (int i = 0; i < 8; i++) a[i] = As[ty * 8 + i][kk];
            float4 b0 = *(float4*)&Bs[kk][tx * 8];
            float4 b1 = *(float4*)&Bs[kk][tx * 8 + 4];
            b[0]=b0.x; b[1]=b0.y; b[2]=b0.z; b[3]=b0.w;
            b[4]=b1.x; b[5]=b1.y; b[6]=b1.z; b[7]=b1.w;
#pragma unroll
            for (int i = 0; i < 8; i++)
#pragma unroll
                for (int j = 0; j < 8; j++) acc[i][j] += a[i] * b[j];
        }
        __syncthreads();
    }

#pragma unroll
    for (int i = 0; i < 8; i++) {
        int row = m0 + ty * 8 + i;
        if (row < n) {
            float4 o0 = make_float4(acc[i][0], acc[i][1], acc[i][2], acc[i][3]);
            float4 o1 = make_float4(acc[i][4], acc[i][5], acc[i][6], acc[i][7]);
            *(float4*)(g_h0 + (size_t)row * D_H + tx * 8)     = o0;
            *(float4*)(g_h0 + (size_t)row * D_H + tx * 8 + 4) = o1;
        }
    }
}

// ---------------- prefill1: h1 = h0 * dinv^2 (self-loop, no memset) --------

__global__ void k_pre1(int n) {
    int total = n * (D_H / 4);
    int stride = gridDim.x * blockDim.x;
    for (int t = blockIdx.x * blockDim.x + threadIdx.x; t < total; t += stride) {
        int row = t >> 4;                       // 16 float4 per row
        float di = g_dinv[row];
        float w = di * di;
        float4 v = ((const float4*)g_h0)[t];
        v.x *= w; v.y *= w; v.z *= w; v.w *= w;
        ((float4*)g_h1)[t] = v;
    }
}

// ---------------- agg1: h1[dst] += h0[src] * dinv[s]*dinv[d] ----------------
// One warp per edge; lane handles 2 channels (float2 -> 256B coalesced gather)

__global__ void k_agg1(const int* __restrict__ src,
                       const int* __restrict__ dst, int e) {
    int wid  = (blockIdx.x * blockDim.x + threadIdx.x) >> 5;
    int lane = threadIdx.x & 31;
    int nw   = (gridDim.x * blockDim.x) >> 5;
    for (int ed = wid; ed < e; ed += nw) {
        int s = __ldg(src + ed);
        int d = __ldg(dst + ed);
        float w = g_dinv[s] * g_dinv[d];
        float2 v = ((const float2*)(g_h0 + (size_t)s * D_H))[lane];
        atomicAdd(&g_h1[(size_t)d * D_H + 2 * lane],     v.x * w);
        atomicAdd(&g_h1[(size_t)d * D_H + 2 * lane + 1], v.y * w);
    }
}

// ------------------------------ BN statistics ------------------------------

__global__ void k_stats(int n) {
    __shared__ float ss[D_H], sq[D_H];
    int tid = threadIdx.x;                 // 256 threads
    if (tid < D_H) { ss[tid] = 0.f; sq[tid] = 0.f; }
    __syncthreads();

    int c  = tid & (D_H - 1);
    int r0 = blockIdx.x * 4 + (tid >> 6);  // 4 row-groups per block
    int rstride = gridDim.x * 4;
    float s = 0.f, s2 = 0.f;
    for (int r = r0; r < n; r += rstride) {
        float v = g_h1[(size_t)r * D_H + c];
        s += v; s2 += v * v;
    }
    atomicAdd(&ss[c], s);
    atomicAdd(&sq[c], s2);
    __syncthreads();
    if (tid < D_H) {
        atomicAdd(&g_stats[tid], ss[tid]);
        atomicAdd(&g_stats[D_H + tid], sq[tid]);
    }
}

__global__ void k_finalize(const float* __restrict__ gamma,
                           const float* __restrict__ beta, float inv_n) {
    int c = threadIdx.x;                   // 64 threads
    float mean = g_stats[c] * inv_n;
    float var  = g_stats[D_H + c] * inv_n - mean * mean;
    float inv  = rsqrtf(var + BN_EPS);
    float sc   = gamma[c] * inv;
    g_scale[c] = sc;
    g_shift[c] = beta[c] - mean * sc;      // (b1 cancels inside BN exactly)
}

// -------------- GEMM2: h2 = relu(h1*scale + shift) @ W2 (fused BN) ---------
// Block tile 128x32, 128 threads, thread tile 4x8, whole K=64 in smem.

__global__ void __launch_bounds__(128) k_gemm2(const float* __restrict__ W2,
                                               int n) {
    __shared__ float As[128][69];          // 64 used, pad for conflict-free
    __shared__ float Bs[64][32];
    __shared__ float s_sc[D_H], s_sh[D_H];

    const int tid = threadIdx.x;
    const int m0  = blockIdx.x * 128;

    if (tid < D_H) { s_sc[tid] = g_scale[tid]; s_sh[tid] = g_shift[tid]; }
    __syncthreads();

    // A tile: one row per thread, apply BN + ReLU on load
    {
        int gm = min(m0 + tid, n - 1);
        const float4* rp = (const float4*)(g_h1 + (size_t)gm * D_H);
#pragma unroll
        for (int kq = 0; kq < 16; kq++) {
            float4 v = rp[kq];
            int k = kq * 4;
            As[tid][k + 0] = fmaxf(fmaf(v.x, s_sc[k + 0], s_sh[k + 0]), 0.f);
            As[tid][k + 1] = fmaxf(fmaf(v.y, s_sc[k + 1], s_sh[k + 1]), 0.f);
            As[tid][k + 2] = fmaxf(fmaf(v.z, s_sc[k + 2], s_sh[k + 2]), 0.f);
            As[tid][k + 3] = fmaxf(fmaf(v.w, s_sc[k + 3], s_sh[k + 3]), 0.f);
        }
    }
    // B tile: 64x32 = 512 float4 / 128 thr = 4 each
#pragma unroll
    for (int p = 0; p < 4; p++) {
        int q = p * 128 + tid;
        int kk = q >> 3, nq = q & 7;
        *(float4*)&Bs[kk][nq * 4] =
            *(const float4*)(W2 + (size_t)kk * D_OUT + nq * 4);
    }
    __syncthreads();

    const int ty = tid >> 2;               // 0..31 (4 rows each)
    const int tx = tid & 3;                // 0..3  (8 cols each)
    float acc[4][8];
#pragma unroll
    for (int i = 0; i < 4; i++)
#pragma unroll
        for (int j = 0; j < 8; j++) acc[i][j] = 0.f;

#pragma unroll
    for (int kk = 0; kk < D_H; kk++) {
        float a[4], b[8];
#pragma unroll
        for (int i = 0; i < 4; i++) a[i] = As[ty * 4 + i][kk];
        float4 b0 = *(float4*)&Bs[kk][tx * 8];
        float4 b1 = *(float4*)&Bs[kk][tx * 8 + 4];
        b[0]=b0.x; b[1]=b0.y; b[2]=b0.z; b[3]=b0.w;
        b[4]=b1.x; b[5]=b1.y; b[6]=b1.z; b[7]=b1.w;
#pragma unroll
        for (int i = 0; i < 4; i++)
#pragma unroll
            for (int j = 0; j < 8; j++) acc[i][j] += a[i] * b[j];
    }

#pragma unroll
    for (int i = 0; i < 4; i++) {
        int row = m0 + ty * 4 + i;
        if (row < n) {
            float4 o0 = make_float4(acc[i][0], acc[i][1], acc[i][2], acc[i][3]);
            float4 o1 = make_float4(acc[i][4], acc[i][5], acc[i][6], acc[i][7]);
            *(float4*)(g_h2 + (size_t)row * D_OUT + tx * 8)     = o0;
            *(float4*)(g_h2 + (size_t)row * D_OUT + tx * 8 + 4) = o1;
        }
    }
}

// ---------- prefill2: out = h2 * dinv^2 + b2 (self-loop + bias) -------------

__global__ void k_pre2(int n, float* __restrict__ out,
                       const float* __restrict__ b2) {
    int total = n * (D_OUT / 4);
    int stride = gridDim.x * blockDim.x;
    for (int t = blockIdx.x * blockDim.x + threadIdx.x; t < total; t += stride) {
        int row = t >> 3;                   // 8 float4 per row
        int cq  = t & 7;
        float di = g_dinv[row];
        float w = di * di;
        float4 v = ((const float4*)g_h2)[t];
        float4 b = ((const float4*)b2)[cq];
        v.x = fmaf(v.x, w, b.x);
        v.y = fmaf(v.y, w, b.y);
        v.z = fmaf(v.z, w, b.z);
        v.w = fmaf(v.w, w, b.w);
        ((float4*)out)[t] = v;
    }
}

// ---------------- agg2: out[dst] += h2[src] * dinv[s]*dinv[d] ---------------
// Half-warp per edge; lane handles float2 (128B coalesced gather per edge)

__global__ void k_agg2(const int* __restrict__ src,
                       const int* __restrict__ dst, int e,
                       float* __restrict__ out) {
    int hw = (blockIdx.x * blockDim.x + threadIdx.x) >> 4;
    int j  = threadIdx.x & 15;
    int nh = (gridDim.x * blockDim.x) >> 4;
    for (int ed = hw; ed < e; ed += nh) {
        int s = __ldg(src + ed);
        int d = __ldg(dst + ed);
        float w = g_dinv[s] * g_dinv[d];
        float2 v = ((const float2*)(g_h2 + (size_t)s * D_OUT))[j];
        atomicAdd(&out[(size_t)d * D_OUT + 2 * j],     v.x * w);
        atomicAdd(&out[(size_t)d * D_OUT + 2 * j + 1], v.y * w);
    }
}

// ---------------------------------------------------------------------------

extern "C" void kernel_launch(void* const* d_in, const int* in_sizes, int n_in,
                              void* d_out, int out_size) {
    const float* x     = (const float*)d_in[0];
    const int*   edge  = (const int*)  d_in[1];
    const float* W1    = (const float*)d_in[2];
    // d_in[3] = b1 : cancels exactly inside batchnorm, unused
    const float* gamma = (const float*)d_in[4];
    const float* beta  = (const float*)d_in[5];
    const float* W2    = (const float*)d_in[6];
    const float* b2    = (const float*)d_in[7];
    float* out = (float*)d_out;

    const int n = in_sizes[0] / D_IN;
    const int e = in_sizes[1] / 2;
    const int* src = edge;       // edge_index[0]
    const int* dst = edge + e;   // edge_index[1]

    // degrees + symmetric norm
    k_zero_deg<<<(n + 255) / 256, 256>>>(n);
    k_deg<<<2048, 256>>>(dst, e);
    k_dinv<<<(n + 255) / 256, 256>>>(n);

    // layer 1
    k_gemm1<<<(n + 127) / 128, 128>>>(x, W1, n);
    k_pre1<<<2048, 256>>>(n);
    k_agg1<<<4096, 256>>>(src, dst, e);

    // batchnorm stats
    k_stats<<<256, 256>>>(n);
    k_finalize<<<1, 64>>>(gamma, beta, 1.0f / (float)n);

    // layer 2 (BN + ReLU fused into GEMM2 A-load)
    k_gemm2<<<(n + 127) / 128, 128>>>(W2, n);
    k_pre2<<<2048, 256>>>(n, out, b2);
    k_agg2<<<4096, 256>>>(src, dst, e, out);
}